// round 6
// baseline (speedup 1.0000x reference)
#include <cuda_runtime.h>
#include <cstdint>

#define NUM_ROWS 1000000
#define DIM 128
#define KPROBES 8

__global__ __launch_bounds__(256) void bloom_embed_kernel(
    const void* __restrict__ t_raw,
    const float* __restrict__ W,
    float* __restrict__ out,
    int n_tokens)
{
    // One warp handles TWO tokens -> 16 independent row gathers in flight
    // per warp (probe MLP doubled vs the 1-token/warp version).
    int gwarp = (blockIdx.x * blockDim.x + threadIdx.x) >> 5;
    int lane  = threadIdx.x & 31;
    int tok_base = gwarp * 2;
    if (tok_base >= n_tokens) return;
    bool have2 = (tok_base + 1) < n_tokens;

    // --- inline dtype detection (int64 vs int32 token storage) ---
    unsigned long long probe =
        ((const unsigned long long*)t_raw)[lane & 3];
    unsigned ball = __ballot_sync(0xffffffffu, (probe >> 32) == 0ULL);
    bool t_is_i64 = (ball == 0xffffffffu);

    // --- load both tokens ---
    long long tok0, tok1;
    if (t_is_i64) {
        const long long* tp = (const long long*)t_raw;
        tok0 = tp[tok_base];
        tok1 = have2 ? tp[tok_base + 1] : tok0;
    } else {
        const int* tp = (const int*)t_raw;
        tok0 = (long long)tp[tok_base];
        tok1 = have2 ? (long long)tp[tok_base + 1] : tok0;
    }

    // --- hash: lanes 0..7 -> token0 probes, lanes 8..15 -> token1 probes
    //     (lanes 16..31 replicate; harmless) ---
    long long tsel = (lane & 8) ? tok1 : tok0;
    long long h = tsel + (long long)(lane & 7);
    h = (long long)(((unsigned long long)((h >> 16) ^ h)) * 73244475ULL);
    h = (long long)(((unsigned long long)((h >> 16) ^ h)) * 73244475ULL);
    h = (h >> 16) ^ h;
    long long m = h % (long long)NUM_ROWS;
    if (m < 0) m += NUM_ROWS;
    int idx = (int)m;

    // broadcast both index sets
    int rid0[KPROBES], rid1[KPROBES];
#pragma unroll
    for (int k = 0; k < KPROBES; k++) {
        rid0[k] = __shfl_sync(0xffffffffu, idx, k);
        rid1[k] = __shfl_sync(0xffffffffu, idx, 8 + k);
    }

    // --- front-batched gather: 16 independent LDG.128 per lane ---
    const int col = lane * 4;
    float4 v0[KPROBES], v1[KPROBES];
#pragma unroll
    for (int k = 0; k < KPROBES; k++)
        v0[k] = __ldcg(reinterpret_cast<const float4*>(
                    W + (size_t)rid0[k] * DIM + col));
#pragma unroll
    for (int k = 0; k < KPROBES; k++)
        v1[k] = __ldcg(reinterpret_cast<const float4*>(
                    W + (size_t)rid1[k] * DIM + col));

    float4 a0 = v0[0], a1 = v1[0];
#pragma unroll
    for (int k = 1; k < KPROBES; k++) {
        a0.x += v0[k].x; a0.y += v0[k].y; a0.z += v0[k].z; a0.w += v0[k].w;
        a1.x += v1[k].x; a1.y += v1[k].y; a1.z += v1[k].z; a1.w += v1[k].w;
    }
    const float s = 1.0f / (float)KPROBES;
    a0.x *= s; a0.y *= s; a0.z *= s; a0.w *= s;
    a1.x *= s; a1.y *= s; a1.z *= s; a1.w *= s;

    *reinterpret_cast<float4*>(out + (size_t)tok_base * DIM + col) = a0;
    if (have2)
        *reinterpret_cast<float4*>(out + (size_t)(tok_base + 1) * DIM + col) = a1;
}

extern "C" void kernel_launch(void* const* d_in, const int* in_sizes, int n_in,
                              void* d_out, int out_size)
{
    // Robust input selection: t is the small tensor, W the big one.
    int ti = 0, wi = 1;
    if (n_in >= 2 && in_sizes[0] > in_sizes[1]) { ti = 1; wi = 0; }

    const void*  t = d_in[ti];
    const float* W = (const float*)d_in[wi];
    float*     out = (float*)d_out;

    int n_tokens = in_sizes[ti];                     // 65536
    int n_warps  = (n_tokens + 1) / 2;               // 2 tokens per warp
    int threads  = 256;                              // 8 warps per block
    int blocks   = (n_warps * 32 + threads - 1) / threads;
    bloom_embed_kernel<<<blocks, threads>>>(t, W, out, n_tokens);
}

// round 7
// speedup vs baseline: 1.0056x; 1.0056x over previous
#include <cuda_runtime.h>
#include <cstdint>

#define NUM_ROWS 1000000
#define DIM 128
#define KPROBES 8

__global__ __launch_bounds__(256) void bloom_embed_kernel(
    const void* __restrict__ t_raw,
    const float* __restrict__ W,
    float* __restrict__ out,
    int n_tokens)
{
    int gwarp = (blockIdx.x * blockDim.x + threadIdx.x) >> 5;
    int lane  = threadIdx.x & 31;
    if (gwarp >= n_tokens) return;

    // --- inline dtype detection (int64 vs int32 token storage) ---
    // Tokens are uniform in [0, 1e9). If stored int64, the high 32 bits of
    // every 8-byte word are zero. If stored int32, each 8-byte word's high
    // half is another random token (zero w.p. ~1e-9). Lanes check the first
    // 4 words (lane & 3); all-hi-zero across the warp => int64.
    unsigned long long probe =
        ((const unsigned long long*)t_raw)[lane & 3];
    unsigned ball = __ballot_sync(0xffffffffu, (probe >> 32) == 0ULL);
    bool t_is_i64 = (ball == 0xffffffffu);

    // --- load token ---
    long long tok;
    if (t_is_i64)
        tok = ((const long long*)t_raw)[gwarp];
    else
        tok = (long long)((const int*)t_raw)[gwarp];

    // --- hash: lanes 0..7 (replicated x4) each compute one probe ---
    long long h = tok + (long long)(lane & 7);
    // Mueller hash with int64 wrapping semantics (arith shift, wrap-mul).
    h = (long long)(((unsigned long long)((h >> 16) ^ h)) * 73244475ULL);
    h = (long long)(((unsigned long long)((h >> 16) ^ h)) * 73244475ULL);
    h = (h >> 16) ^ h;
    long long m = h % (long long)NUM_ROWS;
    if (m < 0) m += NUM_ROWS;            // Python/jnp mod: sign of divisor
    int idx = (int)m;

    // broadcast the 8 probe indices to all lanes
    int rid[KPROBES];
#pragma unroll
    for (int k = 0; k < KPROBES; k++)
        rid[k] = __shfl_sync(0xffffffffu, idx, k);

    // --- front-batched gather: 8 independent LDG.128 per lane (MLP=8) ---
    // __ldcg: L2-only caching. W rows are random within 512 MB -> L1 hit
    // rate ~0; skipping L1 allocation avoids useless fills/evictions and
    // L1tex wavefront overhead.
    const int col = lane * 4;
    float4 v[KPROBES];
#pragma unroll
    for (int k = 0; k < KPROBES; k++)
        v[k] = __ldcg(reinterpret_cast<const float4*>(
                   W + (size_t)rid[k] * DIM + col));

    float4 acc = v[0];
#pragma unroll
    for (int k = 1; k < KPROBES; k++) {
        acc.x += v[k].x; acc.y += v[k].y; acc.z += v[k].z; acc.w += v[k].w;
    }
    const float s = 1.0f / (float)KPROBES;
    acc.x *= s; acc.y *= s; acc.z *= s; acc.w *= s;

    *reinterpret_cast<float4*>(out + (size_t)gwarp * DIM + col) = acc;
}

extern "C" void kernel_launch(void* const* d_in, const int* in_sizes, int n_in,
                              void* d_out, int out_size)
{
    // Robust input selection: t is the small tensor (65,536 elements),
    // W is the big one (128,000,000 elements), regardless of metadata order.
    int ti = 0, wi = 1;
    if (n_in >= 2 && in_sizes[0] > in_sizes[1]) { ti = 1; wi = 0; }

    const void*  t = d_in[ti];
    const float* W = (const float*)d_in[wi];
    float*     out = (float*)d_out;

    int n_tokens = in_sizes[ti];                     // 65536

    int threads = 256;                               // 8 warps -> 8 tokens/block
    int blocks = (n_tokens * 32 + threads - 1) / threads;
    bloom_embed_kernel<<<blocks, threads>>>(t, W, out, n_tokens);
}